// round 8
// baseline (speedup 1.0000x reference)
#include <cuda_runtime.h>
#include <cuda_bf16.h>
#include <math.h>
#include <stdint.h>

#define TLEN  64
#define BSZ   32
#define NROWS 2048
#define HID   1024
#define SLEN  200
#define VTGT  32000
#define VEXT  2000
#define VOUT  34000
#define NT_N  250          // N tiles of 128

// ---------------------------------------------------------------------------
// device scratch
// ---------------------------------------------------------------------------
__device__ float g_logcopy[NROWS];
__device__ float g_omc[NROWS];
__device__ float2 g_part[(size_t)NROWS * NT_N];     // per-(row, ntile) softmax partials
__device__ __align__(128) __nv_bfloat16 g_Ahi[(size_t)NROWS * HID];
__device__ __align__(128) __nv_bfloat16 g_Alo[(size_t)NROWS * HID];
__device__ __align__(128) __nv_bfloat16 g_Bhi[(size_t)VTGT * HID];

// ---------------------------------------------------------------------------
// helpers
// ---------------------------------------------------------------------------
__device__ __forceinline__ uint32_t smem_u32(const void* p) {
    uint32_t a;
    asm("{ .reg .u64 t; cvta.to.shared.u64 t, %1; cvt.u32.u64 %0, t; }" : "=r"(a) : "l"(p));
    return a;
}
__device__ __forceinline__ void cp_async16(uint32_t dst, const void* src) {
    asm volatile("cp.async.cg.shared.global [%0], [%1], 16;" :: "r"(dst), "l"(src) : "memory");
}
#define CP_COMMIT() asm volatile("cp.async.commit_group;" ::: "memory")
#define CP_WAIT1()  asm volatile("cp.async.wait_group 1;" ::: "memory")

__device__ __forceinline__ void ldsm_x4(uint32_t* r, uint32_t addr) {
    asm volatile("ldmatrix.sync.aligned.m8n8.x4.shared.b16 {%0,%1,%2,%3}, [%4];"
                 : "=r"(r[0]), "=r"(r[1]), "=r"(r[2]), "=r"(r[3]) : "r"(addr));
}
__device__ __forceinline__ void mma_bf16(float* c, const uint32_t* a, uint32_t b0, uint32_t b1) {
    asm volatile(
        "mma.sync.aligned.m16n8k16.row.col.f32.bf16.bf16.f32 "
        "{%0,%1,%2,%3}, {%4,%5,%6,%7}, {%8,%9}, {%0,%1,%2,%3};"
        : "+f"(c[0]), "+f"(c[1]), "+f"(c[2]), "+f"(c[3])
        : "r"(a[0]), "r"(a[1]), "r"(a[2]), "r"(a[3]), "r"(b0), "r"(b1));
}

// ---------------------------------------------------------------------------
// pack A: fp32 -> bf16 hi + lo
// ---------------------------------------------------------------------------
__global__ __launch_bounds__(256) void pack_split(const float* __restrict__ src,
                                                  __nv_bfloat16* __restrict__ hi,
                                                  __nv_bfloat16* __restrict__ lo,
                                                  int n4) {
    int stride = gridDim.x * blockDim.x;
    for (int i = blockIdx.x * blockDim.x + threadIdx.x; i < n4; i += stride) {
        float4 v = ((const float4*)src)[i];
        float x[4] = {v.x, v.y, v.z, v.w};
        ushort4 h, l;
        unsigned short* hp = (unsigned short*)&h;
        unsigned short* lp = (unsigned short*)&l;
#pragma unroll
        for (int j = 0; j < 4; j++) {
            __nv_bfloat16 hb = __float2bfloat16(x[j]);
            __nv_bfloat16 lb = __float2bfloat16(x[j] - __bfloat162float(hb));
            hp[j] = *(unsigned short*)&hb;
            lp[j] = *(unsigned short*)&lb;
        }
        ((ushort4*)hi)[i] = h;
        ((ushort4*)lo)[i] = l;
    }
}

// pack B: fp32 -> bf16 hi only
__global__ __launch_bounds__(256) void pack_hi(const float* __restrict__ src,
                                               __nv_bfloat16* __restrict__ hi,
                                               int n4) {
    int stride = gridDim.x * blockDim.x;
    for (int i = blockIdx.x * blockDim.x + threadIdx.x; i < n4; i += stride) {
        float4 v = ((const float4*)src)[i];
        ushort4 h;
        unsigned short* hp = (unsigned short*)&h;
        hp[0] = __bfloat16_as_ushort(__float2bfloat16(v.x));
        hp[1] = __bfloat16_as_ushort(__float2bfloat16(v.y));
        hp[2] = __bfloat16_as_ushort(__float2bfloat16(v.z));
        hp[3] = __bfloat16_as_ushort(__float2bfloat16(v.w));
        ((ushort4*)hi)[i] = h;
    }
}

// ---------------------------------------------------------------------------
// GEMM: out[m, n] = A[m,:] . B[n,:] + bias[n]   (+ per-(row,ntile) softmax partials)
// BM=128, BN=128, BK=32, 256 threads (8 warps: 4M x 2N, warp tile 32x64)
// 2-term split: Ah.Bh + Al.Bh ; 3 stages, 2 CTAs/SM
// stage smem: Ah(10240) | Al(10240) | Bh(10240) = 30720B
// ---------------------------------------------------------------------------
#define STAGE_B   30720
#define SMEM_GEMM (3 * STAGE_B)

__global__ __launch_bounds__(256, 2) void gemm_mma(const float* __restrict__ bias,
                                                   float* __restrict__ out) {
    extern __shared__ unsigned char smem[];
    const uint32_t sb = smem_u32(smem);
    const int tid = threadIdx.x;
    const int wid = tid >> 5, lid = tid & 31;
    const int wm = wid & 3;          // 0..3  (32-row slice)
    const int wn = wid >> 2;         // 0..1  (64-col slice)
    const int m0 = blockIdx.x * 128;
    const int n0 = blockIdx.y * 128;

    // persistent per-thread load state (row = tid>>1, two 16B chunks per matrix)
    const int lr = tid >> 1;
    const uint32_t doff = (uint32_t)lr * 80 + (uint32_t)(tid & 1) * 32;
    const __nv_bfloat16* pA  = g_Ahi + (size_t)(m0 + lr) * HID + (tid & 1) * 16;
    const __nv_bfloat16* pAl = g_Alo + (size_t)(m0 + lr) * HID + (tid & 1) * 16;
    const __nv_bfloat16* pB  = g_Bhi + (size_t)(n0 + lr) * HID + (tid & 1) * 16;

#define ISSUE_STAGE(bufidx) do {                                   \
        uint32_t d = sb + (bufidx) * STAGE_B + doff;               \
        cp_async16(d,             pA);                             \
        cp_async16(d + 16,        pA + 8);                         \
        cp_async16(d + 10240,     pAl);                            \
        cp_async16(d + 10256,     pAl + 8);                        \
        cp_async16(d + 20480,     pB);                             \
        cp_async16(d + 20496,     pB + 8);                         \
        pA += 32; pAl += 32; pB += 32;                             \
    } while (0)

    float acc[2][8][4] = {};

    ISSUE_STAGE(0); CP_COMMIT();
    ISSUE_STAGE(1); CP_COMMIT();

    const int lrow = lid & 15;
    const int lcol = (lid >> 4) << 3;     // 0 or 8
    const uint32_t a_row_off = (uint32_t)(wm * 32 + lrow) * 80;
    const uint32_t b_row_off = 20480u + (uint32_t)(wn * 64 + lrow) * 80;

    int buf = 0, nbuf = 2;
    for (int kt = 0; kt < 32; kt++) {
        CP_WAIT1();
        __syncthreads();
        if (kt < 30) ISSUE_STAGE(nbuf);
        CP_COMMIT();
        nbuf = buf;                       // buffer freed after this kt's compute

        const uint32_t st = sb + buf * STAGE_B;
#pragma unroll
        for (int kk = 0; kk < 32; kk += 16) {
            const uint32_t coff = (uint32_t)(kk + lcol) * 2;
            uint32_t ah[2][4], al[2][4], bh[4][4];
#pragma unroll
            for (int mi = 0; mi < 2; mi++) {
                uint32_t ao = st + a_row_off + (uint32_t)(mi * 16) * 80 + coff;
                ldsm_x4(ah[mi], ao);
                ldsm_x4(al[mi], ao + 10240);
            }
#pragma unroll
            for (int g = 0; g < 4; g++)
                ldsm_x4(bh[g], st + b_row_off + (uint32_t)(g * 16) * 80 + coff);
#pragma unroll
            for (int mi = 0; mi < 2; mi++)
#pragma unroll
                for (int g = 0; g < 4; g++)
#pragma unroll
                    for (int j = 0; j < 2; j++)
                        mma_bf16(acc[mi][2 * g + j], ah[mi], bh[g][j], bh[g][2 + j]);
#pragma unroll
            for (int mi = 0; mi < 2; mi++)
#pragma unroll
                for (int g = 0; g < 4; g++)
#pragma unroll
                    for (int j = 0; j < 2; j++)
                        mma_bf16(acc[mi][2 * g + j], al[mi], bh[g][j], bh[g][2 + j]);
        }
        buf = (buf + 1) % 3;
    }

    // ---- epilogue: bias add + store + per-row softmax partials ----
    const int qrow = lid >> 2;
    const int qcol = (lid & 3) * 2;
#pragma unroll
    for (int ni = 0; ni < 8; ni++) {
        const int gn = n0 + wn * 64 + ni * 8 + qcol;
        const float b0 = __ldg(&bias[gn]);
        const float b1 = __ldg(&bias[gn + 1]);
#pragma unroll
        for (int mi = 0; mi < 2; mi++) {
            const int gm = m0 + wm * 32 + mi * 16 + qrow;
            acc[mi][ni][0] += b0; acc[mi][ni][1] += b1;
            acc[mi][ni][2] += b0; acc[mi][ni][3] += b1;
            *(float2*)&out[(size_t)gm * VOUT + gn] = make_float2(acc[mi][ni][0], acc[mi][ni][1]);
            *(float2*)&out[(size_t)(gm + 8) * VOUT + gn] = make_float2(acc[mi][ni][2], acc[mi][ni][3]);
        }
    }

    // per-row (max, sum exp) over this CTA's 128-col slice
    __syncthreads();                       // smem no longer read; reuse as [128][2] float2
    float2* sm2 = (float2*)smem;
#pragma unroll
    for (int mi = 0; mi < 2; mi++)
#pragma unroll
        for (int h = 0; h < 2; h++) {
            float m = -1e30f;
#pragma unroll
            for (int ni = 0; ni < 8; ni++)
                m = fmaxf(m, fmaxf(acc[mi][ni][2 * h], acc[mi][ni][2 * h + 1]));
            float s = 0.f;
#pragma unroll
            for (int ni = 0; ni < 8; ni++)
                s += __expf(acc[mi][ni][2 * h] - m) + __expf(acc[mi][ni][2 * h + 1] - m);
#pragma unroll
            for (int o = 1; o <= 2; o <<= 1) {
                float om = __shfl_xor_sync(0xffffffffu, m, o);
                float os = __shfl_xor_sync(0xffffffffu, s, o);
                float nm = fmaxf(m, om);
                s = s * __expf(m - nm) + os * __expf(om - nm);
                m = nm;
            }
            if ((lid & 3) == 0)
                sm2[(wm * 32 + mi * 16 + h * 8 + qrow) * 2 + wn] = make_float2(m, s);
        }
    __syncthreads();
    if (tid < 128) {
        float2 p0 = sm2[tid * 2];
        float2 p1 = sm2[tid * 2 + 1];
        float nm = fmaxf(p0.x, p1.x);
        float s = p0.y * __expf(p0.x - nm) + p1.y * __expf(p1.x - nm);
        g_part[(size_t)(m0 + tid) * NT_N + blockIdx.y] = make_float2(nm, s);
    }
}

// ---------------------------------------------------------------------------
// copy gate: one warp per row
// ---------------------------------------------------------------------------
__global__ void copy_gate_kernel(const float* __restrict__ h,
                                 const float* __restrict__ w_copy,
                                 const float* __restrict__ b_copy) {
    int warp = (blockIdx.x * blockDim.x + threadIdx.x) >> 5;
    int lane = threadIdx.x & 31;
    if (warp >= NROWS) return;
    const float* hr = h + (size_t)warp * HID;
    float s = 0.f;
#pragma unroll 8
    for (int i = lane; i < HID; i += 32) s += hr[i] * w_copy[i];
#pragma unroll
    for (int off = 16; off; off >>= 1) s += __shfl_xor_sync(0xffffffffu, s, off);
    if (lane == 0) {
        float z = s + b_copy[0];
        float c = 1.f / (1.f + expf(-z));
        g_logcopy[warp] = logf(fminf(fmaxf(c, 0.001f), 0.999f));
        g_omc[warp]     = 1.f - c;
    }
}

// ---------------------------------------------------------------------------
// softmax finalize: reduce 250 partials per row, then add-sweep
// ---------------------------------------------------------------------------
__global__ __launch_bounds__(256) void softmax_fin(float* __restrict__ out) {
    const int row = blockIdx.x;
    const int tid = threadIdx.x;
    __shared__ float rm[256], rs[256];

    float m = -1e30f, s = 0.f;
    if (tid < NT_N) {
        float2 p = g_part[(size_t)row * NT_N + tid];
        m = p.x; s = p.y;
    }
    rm[tid] = m; rs[tid] = s;
    __syncthreads();
#pragma unroll
    for (int st = 128; st; st >>= 1) {
        if (tid < st) {
            float m2 = rm[tid + st], s2 = rs[tid + st];
            float nm = fmaxf(rm[tid], m2);
            rs[tid] = rs[tid] * __expf(rm[tid] - nm) + s2 * __expf(m2 - nm);
            rm[tid] = nm;
        }
        __syncthreads();
    }
    const float add = g_logcopy[row] - (rm[0] + logf(rs[0]));

    float4* q4 = (float4*)(out + (size_t)row * VOUT);
    for (int v = tid; v < VTGT / 4; v += 256) {
        float4 x = q4[v];
        x.x += add; x.y += add; x.z += add; x.w += add;
        q4[v] = x;
    }
}

// ---------------------------------------------------------------------------
// ext-vocab scatter
// ---------------------------------------------------------------------------
__global__ __launch_bounds__(256) void ext_kernel(const float* __restrict__ attn,
                                                  const int* __restrict__ c2e,
                                                  float* __restrict__ out) {
    const int row = blockIdx.x;
    const int b   = row & (BSZ - 1);
    const int tid = threadIdx.x;
    __shared__ float ext[VEXT];

    for (int e = tid; e < VEXT; e += 256) ext[e] = 0.f;
    __syncthreads();

    const float omc = g_omc[row];
    for (int s = tid; s < SLEN; s += 256) {
        int idx = c2e[s * BSZ + b];
        if (idx != 0)
            atomicAdd(&ext[idx], attn[(size_t)row * SLEN + s] * omc);
    }
    __syncthreads();

    float* p = out + (size_t)row * VOUT + VTGT;
    for (int e = tid; e < VEXT; e += 256)
        p[e] = logf(fminf(fmaxf(ext[e], 0.001f), 0.999f));
}

// ---------------------------------------------------------------------------
extern "C" void kernel_launch(void* const* d_in, const int* in_sizes, int n_in,
                              void* d_out, int out_size) {
    const float* hidden  = (const float*)d_in[0];
    const float* attn    = (const float*)d_in[1];
    const int*   c2e     = (const int*)  d_in[2];
    const float* W_out   = (const float*)d_in[3];
    const float* b_out   = (const float*)d_in[4];
    const float* w_copy  = (const float*)d_in[5];
    const float* b_copy  = (const float*)d_in[6];
    float* out = (float*)d_out;

    __nv_bfloat16 *Ahi, *Alo, *Bhi;
    cudaGetSymbolAddress((void**)&Ahi, g_Ahi);
    cudaGetSymbolAddress((void**)&Alo, g_Alo);
    cudaGetSymbolAddress((void**)&Bhi, g_Bhi);

    cudaFuncSetAttribute(gemm_mma, cudaFuncAttributeMaxDynamicSharedMemorySize, SMEM_GEMM);

    copy_gate_kernel<<<NROWS / 8, 256>>>(hidden, w_copy, b_copy);
    pack_split<<<256, 256>>>(hidden, Ahi, Alo, NROWS * HID / 4);
    pack_hi<<<2048, 256>>>(W_out, Bhi, VTGT * HID / 4);
    gemm_mma<<<dim3(NROWS / 128, VTGT / 128), 256, SMEM_GEMM>>>(b_out, out);
    ext_kernel<<<NROWS, 256>>>(attn, c2e, out);
    softmax_fin<<<NROWS, 256>>>(out);
}

// round 9
// speedup vs baseline: 1.0587x; 1.0587x over previous
#include <cuda_runtime.h>
#include <cuda_bf16.h>
#include <math.h>
#include <stdint.h>

#define TLEN  64
#define BSZ   32
#define NROWS 2048
#define HID   1024
#define SLEN  200
#define VTGT  32000
#define VEXT  2000
#define VOUT  34000
#define NT_N  125          // N tiles of 256

// ---------------------------------------------------------------------------
// device scratch
// ---------------------------------------------------------------------------
__device__ float g_logcopy[NROWS];
__device__ float g_omc[NROWS];
__device__ float2 g_part[(size_t)NROWS * NT_N];
__device__ __align__(128) __nv_bfloat16 g_Ahi[(size_t)NROWS * HID];
__device__ __align__(128) __nv_bfloat16 g_Alo[(size_t)NROWS * HID];
__device__ __align__(128) __nv_bfloat16 g_Bhi[(size_t)VTGT * HID];

// ---------------------------------------------------------------------------
// helpers
// ---------------------------------------------------------------------------
__device__ __forceinline__ uint32_t smem_u32(const void* p) {
    uint32_t a;
    asm("{ .reg .u64 t; cvta.to.shared.u64 t, %1; cvt.u32.u64 %0, t; }" : "=r"(a) : "l"(p));
    return a;
}
__device__ __forceinline__ void cp_async16(uint32_t dst, const void* src) {
    asm volatile("cp.async.cg.shared.global [%0], [%1], 16;" :: "r"(dst), "l"(src) : "memory");
}
#define CP_COMMIT() asm volatile("cp.async.commit_group;" ::: "memory")
#define CP_WAIT2()  asm volatile("cp.async.wait_group 2;" ::: "memory")

__device__ __forceinline__ void ldsm_x4(uint32_t* r, uint32_t addr) {
    asm volatile("ldmatrix.sync.aligned.m8n8.x4.shared.b16 {%0,%1,%2,%3}, [%4];"
                 : "=r"(r[0]), "=r"(r[1]), "=r"(r[2]), "=r"(r[3]) : "r"(addr));
}
__device__ __forceinline__ void mma_bf16(float* c, const uint32_t* a, uint32_t b0, uint32_t b1) {
    asm volatile(
        "mma.sync.aligned.m16n8k16.row.col.f32.bf16.bf16.f32 "
        "{%0,%1,%2,%3}, {%4,%5,%6,%7}, {%8,%9}, {%0,%1,%2,%3};"
        : "+f"(c[0]), "+f"(c[1]), "+f"(c[2]), "+f"(c[3])
        : "r"(a[0]), "r"(a[1]), "r"(a[2]), "r"(a[3]), "r"(b0), "r"(b1));
}

// ---------------------------------------------------------------------------
// pack A: fp32 -> bf16 hi + lo
// ---------------------------------------------------------------------------
__global__ __launch_bounds__(256) void pack_split(const float* __restrict__ src,
                                                  __nv_bfloat16* __restrict__ hi,
                                                  __nv_bfloat16* __restrict__ lo,
                                                  int n4) {
    int stride = gridDim.x * blockDim.x;
    for (int i = blockIdx.x * blockDim.x + threadIdx.x; i < n4; i += stride) {
        float4 v = ((const float4*)src)[i];
        float x[4] = {v.x, v.y, v.z, v.w};
        ushort4 h, l;
        unsigned short* hp = (unsigned short*)&h;
        unsigned short* lp = (unsigned short*)&l;
#pragma unroll
        for (int j = 0; j < 4; j++) {
            __nv_bfloat16 hb = __float2bfloat16(x[j]);
            __nv_bfloat16 lb = __float2bfloat16(x[j] - __bfloat162float(hb));
            hp[j] = *(unsigned short*)&hb;
            lp[j] = *(unsigned short*)&lb;
        }
        ((ushort4*)hi)[i] = h;
        ((ushort4*)lo)[i] = l;
    }
}

// pack B: fp32 -> bf16 hi only
__global__ __launch_bounds__(256) void pack_hi(const float* __restrict__ src,
                                               __nv_bfloat16* __restrict__ hi,
                                               int n4) {
    int stride = gridDim.x * blockDim.x;
    for (int i = blockIdx.x * blockDim.x + threadIdx.x; i < n4; i += stride) {
        float4 v = ((const float4*)src)[i];
        ushort4 h;
        unsigned short* hp = (unsigned short*)&h;
        hp[0] = __bfloat16_as_ushort(__float2bfloat16(v.x));
        hp[1] = __bfloat16_as_ushort(__float2bfloat16(v.y));
        hp[2] = __bfloat16_as_ushort(__float2bfloat16(v.z));
        hp[3] = __bfloat16_as_ushort(__float2bfloat16(v.w));
        ((ushort4*)hi)[i] = h;
    }
}

// ---------------------------------------------------------------------------
// GEMM: out[m, n] = A[m,:] . B[n,:] + bias[n]   (+ per-(row,ntile) softmax partials)
// BM=128, BN=256, BK=32, 512 threads (16 warps: 4M x 4N, warp tile 32x64)
// 2-term split: Ah.Bh + Al.Bh ; 4 stages, mainloop unrolled x4
// stage smem: Ah(10240) | Al(10240) | Bh(20480) = 40960B
// ---------------------------------------------------------------------------
#define STAGE_B   40960
#define SMEM_GEMM (4 * STAGE_B)

__global__ __launch_bounds__(512, 1) void gemm_mma(const float* __restrict__ bias,
                                                   float* __restrict__ out) {
    extern __shared__ unsigned char smem[];
    const uint32_t sb = smem_u32(smem);
    const int tid = threadIdx.x;
    const int wid = tid >> 5, lid = tid & 31;
    const int wm = wid & 3;          // 0..3  (32-row slice)
    const int wn = wid >> 2;         // 0..3  (64-col slice)
    const int m0 = blockIdx.x * 128;
    const int n0 = blockIdx.y * 256;

    // persistent per-thread cp.async state
    const int ar = tid >> 2, ac = tid & 3;          // A: 128 rows x 4 chunks
    const int b1r = (512 + tid) >> 2, b1c = (512 + tid) & 3;
    const uint32_t dA  = (uint32_t)ar * 80 + ac * 16;
    const uint32_t dB0 = 20480u + (uint32_t)ar * 80 + ac * 16;      // B rows 0..127
    const uint32_t dB1 = 20480u + (uint32_t)b1r * 80 + b1c * 16;    // B rows 128..255
    const __nv_bfloat16* pA  = g_Ahi + (size_t)(m0 + ar) * HID + ac * 8;
    const __nv_bfloat16* pAl = g_Alo + (size_t)(m0 + ar) * HID + ac * 8;
    const __nv_bfloat16* pB0 = g_Bhi + (size_t)(n0 + ar) * HID + ac * 8;
    const __nv_bfloat16* pB1 = g_Bhi + (size_t)(n0 + b1r) * HID + b1c * 8;

#define ISSUE(bufc) do {                                           \
        const uint32_t d = sb + (bufc) * STAGE_B;                  \
        cp_async16(d + dA,          pA);                           \
        cp_async16(d + dA + 10240,  pAl);                          \
        cp_async16(d + dB0,         pB0);                          \
        cp_async16(d + dB1,         pB1);                          \
        pA += 32; pAl += 32; pB0 += 32; pB1 += 32;                 \
    } while (0)

    float acc[2][8][4] = {};

    ISSUE(0); CP_COMMIT();
    ISSUE(1); CP_COMMIT();
    ISSUE(2); CP_COMMIT();

    const int lrow = lid & 15;
    const int lcol = (lid >> 4) << 3;     // 0 or 8
    const uint32_t a_row_off = (uint32_t)(wm * 32 + lrow) * 80;
    const uint32_t b_row_off = 20480u + (uint32_t)(wn * 64 + lrow) * 80;

#define COMPUTE(bufc) do {                                                         \
        const uint32_t st = sb + (bufc) * STAGE_B;                                 \
        _Pragma("unroll")                                                          \
        for (int kk = 0; kk < 32; kk += 16) {                                      \
            const uint32_t coff = (uint32_t)(kk + lcol) * 2;                       \
            uint32_t ah[2][4], al[2][4], bh[4][4];                                 \
            _Pragma("unroll")                                                      \
            for (int mi = 0; mi < 2; mi++) {                                       \
                uint32_t ao = st + a_row_off + (uint32_t)(mi * 16) * 80 + coff;    \
                ldsm_x4(ah[mi], ao);                                               \
                ldsm_x4(al[mi], ao + 10240);                                       \
            }                                                                      \
            _Pragma("unroll")                                                      \
            for (int g = 0; g < 4; g++)                                            \
                ldsm_x4(bh[g], st + b_row_off + (uint32_t)(g * 16) * 80 + coff);   \
            _Pragma("unroll")                                                      \
            for (int mi = 0; mi < 2; mi++)                                         \
                _Pragma("unroll")                                                  \
                for (int g = 0; g < 4; g++)                                        \
                    _Pragma("unroll")                                              \
                    for (int j = 0; j < 2; j++)                                    \
                        mma_bf16(acc[mi][2 * g + j], ah[mi], bh[g][j], bh[g][2 + j]); \
            _Pragma("unroll")                                                      \
            for (int mi = 0; mi < 2; mi++)                                         \
                _Pragma("unroll")                                                  \
                for (int g = 0; g < 4; g++)                                        \
                    _Pragma("unroll")                                              \
                    for (int j = 0; j < 2; j++)                                    \
                        mma_bf16(acc[mi][2 * g + j], al[mi], bh[g][j], bh[g][2 + j]); \
        }                                                                          \
    } while (0)

#define BODY(kt, j) do {                                   \
        CP_WAIT2();                                        \
        __syncthreads();                                   \
        if ((kt) + (j) + 3 < 32) ISSUE(((j) + 3) & 3);     \
        CP_COMMIT();                                       \
        COMPUTE(j);                                        \
    } while (0)

    for (int kt = 0; kt < 32; kt += 4) {
        BODY(kt, 0);
        BODY(kt, 1);
        BODY(kt, 2);
        BODY(kt, 3);
    }

    // ---- epilogue: bias add + store + per-row softmax partials ----
    const int qrow = lid >> 2;
    const int qcol = (lid & 3) * 2;
#pragma unroll
    for (int ni = 0; ni < 8; ni++) {
        const int gn = n0 + wn * 64 + ni * 8 + qcol;
        const float b0 = __ldg(&bias[gn]);
        const float b1 = __ldg(&bias[gn + 1]);
#pragma unroll
        for (int mi = 0; mi < 2; mi++) {
            const int gm = m0 + wm * 32 + mi * 16 + qrow;
            acc[mi][ni][0] += b0; acc[mi][ni][1] += b1;
            acc[mi][ni][2] += b0; acc[mi][ni][3] += b1;
            *(float2*)&out[(size_t)gm * VOUT + gn] = make_float2(acc[mi][ni][0], acc[mi][ni][1]);
            *(float2*)&out[(size_t)(gm + 8) * VOUT + gn] = make_float2(acc[mi][ni][2], acc[mi][ni][3]);
        }
    }

    // per-row (max, sum exp) over this CTA's 256-col slice
    __syncthreads();
    float2* sm2 = (float2*)smem;
#pragma unroll
    for (int mi = 0; mi < 2; mi++)
#pragma unroll
        for (int h = 0; h < 2; h++) {
            float m = -1e30f;
#pragma unroll
            for (int ni = 0; ni < 8; ni++)
                m = fmaxf(m, fmaxf(acc[mi][ni][2 * h], acc[mi][ni][2 * h + 1]));
            float s = 0.f;
#pragma unroll
            for (int ni = 0; ni < 8; ni++)
                s += __expf(acc[mi][ni][2 * h] - m) + __expf(acc[mi][ni][2 * h + 1] - m);
#pragma unroll
            for (int o = 1; o <= 2; o <<= 1) {
                float om = __shfl_xor_sync(0xffffffffu, m, o);
                float os = __shfl_xor_sync(0xffffffffu, s, o);
                float nm = fmaxf(m, om);
                s = s * __expf(m - nm) + os * __expf(om - nm);
                m = nm;
            }
            if ((lid & 3) == 0)
                sm2[(wm * 32 + mi * 16 + h * 8 + qrow) * 4 + wn] = make_float2(m, s);
        }
    __syncthreads();
    if (tid < 128) {
        float m = -1e30f, s = 0.f;
#pragma unroll
        for (int w = 0; w < 4; w++) {
            float2 p = sm2[tid * 4 + w];
            float nm = fmaxf(m, p.x);
            s = s * __expf(m - nm) + p.y * __expf(p.x - nm);
            m = nm;
        }
        g_part[(size_t)(m0 + tid) * NT_N + blockIdx.y] = make_float2(m, s);
    }
}

// ---------------------------------------------------------------------------
// copy gate: one warp per row
// ---------------------------------------------------------------------------
__global__ void copy_gate_kernel(const float* __restrict__ h,
                                 const float* __restrict__ w_copy,
                                 const float* __restrict__ b_copy) {
    int warp = (blockIdx.x * blockDim.x + threadIdx.x) >> 5;
    int lane = threadIdx.x & 31;
    if (warp >= NROWS) return;
    const float* hr = h + (size_t)warp * HID;
    float s = 0.f;
#pragma unroll 8
    for (int i = lane; i < HID; i += 32) s += hr[i] * w_copy[i];
#pragma unroll
    for (int off = 16; off; off >>= 1) s += __shfl_xor_sync(0xffffffffu, s, off);
    if (lane == 0) {
        float z = s + b_copy[0];
        float c = 1.f / (1.f + expf(-z));
        g_logcopy[warp] = logf(fminf(fmaxf(c, 0.001f), 0.999f));
        g_omc[warp]     = 1.f - c;
    }
}

// ---------------------------------------------------------------------------
// softmax finalize: reduce 125 partials per row, then add-sweep
// ---------------------------------------------------------------------------
__global__ __launch_bounds__(256) void softmax_fin(float* __restrict__ out) {
    const int row = blockIdx.x;
    const int tid = threadIdx.x;
    __shared__ float rm[256], rs[256];

    float m = -1e30f, s = 0.f;
    if (tid < NT_N) {
        float2 p = g_part[(size_t)row * NT_N + tid];
        m = p.x; s = p.y;
    }
    rm[tid] = m; rs[tid] = s;
    __syncthreads();
#pragma unroll
    for (int st = 128; st; st >>= 1) {
        if (tid < st) {
            float m2 = rm[tid + st], s2 = rs[tid + st];
            float nm = fmaxf(rm[tid], m2);
            rs[tid] = rs[tid] * __expf(rm[tid] - nm) + s2 * __expf(m2 - nm);
            rm[tid] = nm;
        }
        __syncthreads();
    }
    const float add = g_logcopy[row] - (rm[0] + logf(rs[0]));

    float4* q4 = (float4*)(out + (size_t)row * VOUT);
    for (int v = tid; v < VTGT / 4; v += 256) {
        float4 x = q4[v];
        x.x += add; x.y += add; x.z += add; x.w += add;
        q4[v] = x;
    }
}

// ---------------------------------------------------------------------------
// ext-vocab scatter
// ---------------------------------------------------------------------------
__global__ __launch_bounds__(256) void ext_kernel(const float* __restrict__ attn,
                                                  const int* __restrict__ c2e,
                                                  float* __restrict__ out) {
    const int row = blockIdx.x;
    const int b   = row & (BSZ - 1);
    const int tid = threadIdx.x;
    __shared__ float ext[VEXT];

    for (int e = tid; e < VEXT; e += 256) ext[e] = 0.f;
    __syncthreads();

    const float omc = g_omc[row];
    for (int s = tid; s < SLEN; s += 256) {
        int idx = c2e[s * BSZ + b];
        if (idx != 0)
            atomicAdd(&ext[idx], attn[(size_t)row * SLEN + s] * omc);
    }
    __syncthreads();

    float* p = out + (size_t)row * VOUT + VTGT;
    for (int e = tid; e < VEXT; e += 256)
        p[e] = logf(fminf(fmaxf(ext[e], 0.001f), 0.999f));
}

// ---------------------------------------------------------------------------
extern "C" void kernel_launch(void* const* d_in, const int* in_sizes, int n_in,
                              void* d_out, int out_size) {
    const float* hidden  = (const float*)d_in[0];
    const float* attn    = (const float*)d_in[1];
    const int*   c2e     = (const int*)  d_in[2];
    const float* W_out   = (const float*)d_in[3];
    const float* b_out   = (const float*)d_in[4];
    const float* w_copy  = (const float*)d_in[5];
    const float* b_copy  = (const float*)d_in[6];
    float* out = (float*)d_out;

    __nv_bfloat16 *Ahi, *Alo, *Bhi;
    cudaGetSymbolAddress((void**)&Ahi, g_Ahi);
    cudaGetSymbolAddress((void**)&Alo, g_Alo);
    cudaGetSymbolAddress((void**)&Bhi, g_Bhi);

    cudaFuncSetAttribute(gemm_mma, cudaFuncAttributeMaxDynamicSharedMemorySize, SMEM_GEMM);

    copy_gate_kernel<<<NROWS / 8, 256>>>(hidden, w_copy, b_copy);
    pack_split<<<256, 256>>>(hidden, Ahi, Alo, NROWS * HID / 4);
    pack_hi<<<2048, 256>>>(W_out, Bhi, VTGT * HID / 4);
    gemm_mma<<<dim3(NROWS / 128, VTGT / 256), 512, SMEM_GEMM>>>(b_out, out);
    ext_kernel<<<NROWS, 256>>>(attn, c2e, out);
    softmax_fin<<<NROWS, 256>>>(out);
}

// round 10
// speedup vs baseline: 1.7513x; 1.6542x over previous
#include <cuda_runtime.h>
#include <cuda_bf16.h>
#include <math.h>
#include <stdint.h>

#define TLEN  64
#define BSZ   32
#define NROWS 2048
#define HID   1024
#define SLEN  200
#define VTGT  32000
#define VEXT  2000
#define VOUT  34000
#define NT_N  125          // N tiles of 256

// ---------------------------------------------------------------------------
// device scratch
// ---------------------------------------------------------------------------
__device__ float g_logcopy[NROWS];
__device__ float g_omc[NROWS];
__device__ float2 g_part[(size_t)NROWS * NT_N];
__device__ __align__(128) __nv_bfloat16 g_Ahi[(size_t)NROWS * HID];
__device__ __align__(128) __nv_bfloat16 g_Bhi[(size_t)VTGT * HID];

// ---------------------------------------------------------------------------
// helpers
// ---------------------------------------------------------------------------
__device__ __forceinline__ uint32_t smem_u32(const void* p) {
    uint32_t a;
    asm("{ .reg .u64 t; cvta.to.shared.u64 t, %1; cvt.u32.u64 %0, t; }" : "=r"(a) : "l"(p));
    return a;
}
__device__ __forceinline__ void cp_async16(uint32_t dst, const void* src) {
    asm volatile("cp.async.cg.shared.global [%0], [%1], 16;" :: "r"(dst), "l"(src) : "memory");
}
#define CP_COMMIT() asm volatile("cp.async.commit_group;" ::: "memory")
#define CP_WAIT2()  asm volatile("cp.async.wait_group 2;" ::: "memory")

__device__ __forceinline__ void ldsm_x4(uint32_t* r, uint32_t addr) {
    asm volatile("ldmatrix.sync.aligned.m8n8.x4.shared.b16 {%0,%1,%2,%3}, [%4];"
                 : "=r"(r[0]), "=r"(r[1]), "=r"(r[2]), "=r"(r[3]) : "r"(addr));
}
__device__ __forceinline__ void mma_bf16(float* c, const uint32_t* a, uint32_t b0, uint32_t b1) {
    asm volatile(
        "mma.sync.aligned.m16n8k16.row.col.f32.bf16.bf16.f32 "
        "{%0,%1,%2,%3}, {%4,%5,%6,%7}, {%8,%9}, {%0,%1,%2,%3};"
        : "+f"(c[0]), "+f"(c[1]), "+f"(c[2]), "+f"(c[3])
        : "r"(a[0]), "r"(a[1]), "r"(a[2]), "r"(a[3]), "r"(b0), "r"(b1));
}

// ---------------------------------------------------------------------------
// pack: fp32 -> bf16 (round-to-nearest)
// ---------------------------------------------------------------------------
__global__ __launch_bounds__(256) void pack_hi(const float* __restrict__ src,
                                               __nv_bfloat16* __restrict__ hi,
                                               int n4) {
    int stride = gridDim.x * blockDim.x;
    for (int i = blockIdx.x * blockDim.x + threadIdx.x; i < n4; i += stride) {
        float4 v = ((const float4*)src)[i];
        ushort4 h;
        unsigned short* hp = (unsigned short*)&h;
        hp[0] = __bfloat16_as_ushort(__float2bfloat16(v.x));
        hp[1] = __bfloat16_as_ushort(__float2bfloat16(v.y));
        hp[2] = __bfloat16_as_ushort(__float2bfloat16(v.z));
        hp[3] = __bfloat16_as_ushort(__float2bfloat16(v.w));
        ((ushort4*)hi)[i] = h;
    }
}

// ---------------------------------------------------------------------------
// GEMM: out[m, n] = A[m,:] . B[n,:] + bias[n]   (+ per-(row,ntile) softmax partials)
// BM=128, BN=256, BK=32, 512 threads (16 warps: 4M x 4N, warp tile 32x64)
// pure bf16 (1-term) ; 4 stages, mainloop unrolled x4
// stage smem: Ah(10240) | Bh(20480) = 30720B
// ---------------------------------------------------------------------------
#define STAGE_B   30720
#define SMEM_GEMM (4 * STAGE_B)

__global__ __launch_bounds__(512, 1) void gemm_mma(const float* __restrict__ bias,
                                                   float* __restrict__ out) {
    extern __shared__ unsigned char smem[];
    const uint32_t sb = smem_u32(smem);
    const int tid = threadIdx.x;
    const int wid = tid >> 5, lid = tid & 31;
    const int wm = wid & 3;          // 0..3  (32-row slice)
    const int wn = wid >> 2;         // 0..3  (64-col slice)
    const int m0 = blockIdx.x * 128;
    const int n0 = blockIdx.y * 256;

    // persistent per-thread cp.async state
    const int ar = tid >> 2, ac = tid & 3;          // A: 128 rows x 4 chunks
    const int b1r = (512 + tid) >> 2, b1c = (512 + tid) & 3;
    const uint32_t dA  = (uint32_t)ar * 80 + ac * 16;
    const uint32_t dB0 = 10240u + (uint32_t)ar * 80 + ac * 16;      // B rows 0..127
    const uint32_t dB1 = 10240u + (uint32_t)b1r * 80 + b1c * 16;    // B rows 128..255
    const __nv_bfloat16* pA  = g_Ahi + (size_t)(m0 + ar) * HID + ac * 8;
    const __nv_bfloat16* pB0 = g_Bhi + (size_t)(n0 + ar) * HID + ac * 8;
    const __nv_bfloat16* pB1 = g_Bhi + (size_t)(n0 + b1r) * HID + b1c * 8;

#define ISSUE(bufc) do {                                           \
        const uint32_t d = sb + (bufc) * STAGE_B;                  \
        cp_async16(d + dA,  pA);                                   \
        cp_async16(d + dB0, pB0);                                  \
        cp_async16(d + dB1, pB1);                                  \
        pA += 32; pB0 += 32; pB1 += 32;                            \
    } while (0)

    float acc[2][8][4] = {};

    ISSUE(0); CP_COMMIT();
    ISSUE(1); CP_COMMIT();
    ISSUE(2); CP_COMMIT();

    const int lrow = lid & 15;
    const int lcol = (lid >> 4) << 3;     // 0 or 8
    const uint32_t a_row_off = (uint32_t)(wm * 32 + lrow) * 80;
    const uint32_t b_row_off = 10240u + (uint32_t)(wn * 64 + lrow) * 80;

#define COMPUTE(bufc) do {                                                         \
        const uint32_t st = sb + (bufc) * STAGE_B;                                 \
        _Pragma("unroll")                                                          \
        for (int kk = 0; kk < 32; kk += 16) {                                      \
            const uint32_t coff = (uint32_t)(kk + lcol) * 2;                       \
            uint32_t ah[2][4], bh[4][4];                                           \
            _Pragma("unroll")                                                      \
            for (int mi = 0; mi < 2; mi++)                                         \
                ldsm_x4(ah[mi], st + a_row_off + (uint32_t)(mi * 16) * 80 + coff); \
            _Pragma("unroll")                                                      \
            for (int g = 0; g < 4; g++)                                            \
                ldsm_x4(bh[g], st + b_row_off + (uint32_t)(g * 16) * 80 + coff);   \
            _Pragma("unroll")                                                      \
            for (int mi = 0; mi < 2; mi++)                                         \
                _Pragma("unroll")                                                  \
                for (int g = 0; g < 4; g++)                                        \
                    _Pragma("unroll")                                              \
                    for (int j = 0; j < 2; j++)                                    \
                        mma_bf16(acc[mi][2 * g + j], ah[mi], bh[g][j], bh[g][2 + j]); \
        }                                                                          \
    } while (0)

#define BODY(kt, j) do {                                   \
        CP_WAIT2();                                        \
        __syncthreads();                                   \
        if ((kt) + (j) + 3 < 32) ISSUE(((j) + 3) & 3);     \
        CP_COMMIT();                                       \
        COMPUTE(j);                                        \
    } while (0)

    for (int kt = 0; kt < 32; kt += 4) {
        BODY(kt, 0);
        BODY(kt, 1);
        BODY(kt, 2);
        BODY(kt, 3);
    }

    // ---- epilogue: bias add + store + per-row softmax partials ----
    const int qrow = lid >> 2;
    const int qcol = (lid & 3) * 2;
#pragma unroll
    for (int ni = 0; ni < 8; ni++) {
        const int gn = n0 + wn * 64 + ni * 8 + qcol;
        const float b0 = __ldg(&bias[gn]);
        const float b1 = __ldg(&bias[gn + 1]);
#pragma unroll
        for (int mi = 0; mi < 2; mi++) {
            const int gm = m0 + wm * 32 + mi * 16 + qrow;
            acc[mi][ni][0] += b0; acc[mi][ni][1] += b1;
            acc[mi][ni][2] += b0; acc[mi][ni][3] += b1;
            *(float2*)&out[(size_t)gm * VOUT + gn] = make_float2(acc[mi][ni][0], acc[mi][ni][1]);
            *(float2*)&out[(size_t)(gm + 8) * VOUT + gn] = make_float2(acc[mi][ni][2], acc[mi][ni][3]);
        }
    }

    // per-row (max, sum exp) over this CTA's 256-col slice
    __syncthreads();
    float2* sm2 = (float2*)smem;
#pragma unroll
    for (int mi = 0; mi < 2; mi++)
#pragma unroll
        for (int h = 0; h < 2; h++) {
            float m = -1e30f;
#pragma unroll
            for (int ni = 0; ni < 8; ni++)
                m = fmaxf(m, fmaxf(acc[mi][ni][2 * h], acc[mi][ni][2 * h + 1]));
            float s = 0.f;
#pragma unroll
            for (int ni = 0; ni < 8; ni++)
                s += __expf(acc[mi][ni][2 * h] - m) + __expf(acc[mi][ni][2 * h + 1] - m);
#pragma unroll
            for (int o = 1; o <= 2; o <<= 1) {
                float om = __shfl_xor_sync(0xffffffffu, m, o);
                float os = __shfl_xor_sync(0xffffffffu, s, o);
                float nm = fmaxf(m, om);
                s = s * __expf(m - nm) + os * __expf(om - nm);
                m = nm;
            }
            if ((lid & 3) == 0)
                sm2[(wm * 32 + mi * 16 + h * 8 + qrow) * 4 + wn] = make_float2(m, s);
        }
    __syncthreads();
    if (tid < 128) {
        float m = -1e30f, s = 0.f;
#pragma unroll
        for (int w = 0; w < 4; w++) {
            float2 p = sm2[tid * 4 + w];
            float nm = fmaxf(m, p.x);
            s = s * __expf(m - nm) + p.y * __expf(p.x - nm);
            m = nm;
        }
        g_part[(size_t)(m0 + tid) * NT_N + blockIdx.y] = make_float2(m, s);
    }
}

// ---------------------------------------------------------------------------
// copy gate: one warp per row
// ---------------------------------------------------------------------------
__global__ void copy_gate_kernel(const float* __restrict__ h,
                                 const float* __restrict__ w_copy,
                                 const float* __restrict__ b_copy) {
    int warp = (blockIdx.x * blockDim.x + threadIdx.x) >> 5;
    int lane = threadIdx.x & 31;
    if (warp >= NROWS) return;
    const float* hr = h + (size_t)warp * HID;
    float s = 0.f;
#pragma unroll 8
    for (int i = lane; i < HID; i += 32) s += hr[i] * w_copy[i];
#pragma unroll
    for (int off = 16; off; off >>= 1) s += __shfl_xor_sync(0xffffffffu, s, off);
    if (lane == 0) {
        float z = s + b_copy[0];
        float c = 1.f / (1.f + expf(-z));
        g_logcopy[warp] = logf(fminf(fmaxf(c, 0.001f), 0.999f));
        g_omc[warp]     = 1.f - c;
    }
}

// ---------------------------------------------------------------------------
// softmax finalize: reduce 125 partials per row, then add-sweep
// ---------------------------------------------------------------------------
__global__ __launch_bounds__(256) void softmax_fin(float* __restrict__ out) {
    const int row = blockIdx.x;
    const int tid = threadIdx.x;
    __shared__ float rm[256], rs[256];

    float m = -1e30f, s = 0.f;
    if (tid < NT_N) {
        float2 p = g_part[(size_t)row * NT_N + tid];
        m = p.x; s = p.y;
    }
    rm[tid] = m; rs[tid] = s;
    __syncthreads();
#pragma unroll
    for (int st = 128; st; st >>= 1) {
        if (tid < st) {
            float m2 = rm[tid + st], s2 = rs[tid + st];
            float nm = fmaxf(rm[tid], m2);
            rs[tid] = rs[tid] * __expf(rm[tid] - nm) + s2 * __expf(m2 - nm);
            rm[tid] = nm;
        }
        __syncthreads();
    }
    const float add = g_logcopy[row] - (rm[0] + logf(rs[0]));

    float4* q4 = (float4*)(out + (size_t)row * VOUT);
    for (int v = tid; v < VTGT / 4; v += 256) {
        float4 x = q4[v];
        x.x += add; x.y += add; x.z += add; x.w += add;
        q4[v] = x;
    }
}

// ---------------------------------------------------------------------------
// ext-vocab scatter
// ---------------------------------------------------------------------------
__global__ __launch_bounds__(256) void ext_kernel(const float* __restrict__ attn,
                                                  const int* __restrict__ c2e,
                                                  float* __restrict__ out) {
    const int row = blockIdx.x;
    const int b   = row & (BSZ - 1);
    const int tid = threadIdx.x;
    __shared__ float ext[VEXT];

    for (int e = tid; e < VEXT; e += 256) ext[e] = 0.f;
    __syncthreads();

    const float omc = g_omc[row];
    for (int s = tid; s < SLEN; s += 256) {
        int idx = c2e[s * BSZ + b];
        if (idx != 0)
            atomicAdd(&ext[idx], attn[(size_t)row * SLEN + s] * omc);
    }
    __syncthreads();

    float* p = out + (size_t)row * VOUT + VTGT;
    for (int e = tid; e < VEXT; e += 256)
        p[e] = logf(fminf(fmaxf(ext[e], 0.001f), 0.999f));
}

// ---------------------------------------------------------------------------
extern "C" void kernel_launch(void* const* d_in, const int* in_sizes, int n_in,
                              void* d_out, int out_size) {
    const float* hidden  = (const float*)d_in[0];
    const float* attn    = (const float*)d_in[1];
    const int*   c2e     = (const int*)  d_in[2];
    const float* W_out   = (const float*)d_in[3];
    const float* b_out   = (const float*)d_in[4];
    const float* w_copy  = (const float*)d_in[5];
    const float* b_copy  = (const float*)d_in[6];
    float* out = (float*)d_out;

    __nv_bfloat16 *Ahi, *Bhi;
    cudaGetSymbolAddress((void**)&Ahi, g_Ahi);
    cudaGetSymbolAddress((void**)&Bhi, g_Bhi);

    cudaFuncSetAttribute(gemm_mma, cudaFuncAttributeMaxDynamicSharedMemorySize, SMEM_GEMM);

    copy_gate_kernel<<<NROWS / 8, 256>>>(hidden, w_copy, b_copy);
    pack_hi<<<256, 256>>>(hidden, Ahi, NROWS * HID / 4);
    pack_hi<<<2048, 256>>>(W_out, Bhi, VTGT * HID / 4);
    gemm_mma<<<dim3(NROWS / 128, VTGT / 256), 512, SMEM_GEMM>>>(b_out, out);
    ext_kernel<<<NROWS, 256>>>(attn, c2e, out);
    softmax_fin<<<NROWS, 256>>>(out);
}